// round 1
// baseline (speedup 1.0000x reference)
#include <cuda_runtime.h>
#include <cuda_bf16.h>

// Problem constants (fixed by the reference's setup_inputs)
#define NTOKEN 150000
#define NINP   64
#define NEDGE  2400000
#define NBL    12800            // B*L = 64*200
#define BMWORDS ((NTOKEN + 31) / 32)

// ---------------------------------------------------------------------------
// Scratch (static __device__ arrays — no allocations allowed)
// ---------------------------------------------------------------------------
__device__ __align__(16) float g_y[NTOKEN * NINP];   // P X
__device__ __align__(16) float g_z[NTOKEN * NINP];   // P (P X), valid at token rows
__device__ float    g_deg[NTOKEN];
__device__ float    g_dinv[NTOKEN];
__device__ float    g_c[NTOKEN];                     // c_i = sum_in norm + dinv^2
__device__ unsigned g_tokbm[BMWORDS];                // token-node bitmap
__device__ float    g_W12[NINP * NINP];              // W1 @ W2
__device__ float    g_bW[NINP];                      // b1 @ W2
__device__ int      g_is64;                          // index arrays stored as int64?

// ---------------------------------------------------------------------------
// Helpers
// ---------------------------------------------------------------------------
__device__ __forceinline__ long long ld_idx(const void* p, long long i, int is64) {
    return is64 ? ((const long long*)p)[i] : (long long)((const int*)p)[i];
}

__device__ __forceinline__ void red_add_v4(float* p, float4 v) {
    asm volatile("red.global.add.v4.f32 [%0], {%1,%2,%3,%4};"
                 :: "l"(p), "f"(v.x), "f"(v.y), "f"(v.z), "f"(v.w) : "memory");
}

// ---------------------------------------------------------------------------
// K0: detect whether index tensors are int64 or int32 in storage.
// If int32 data is read as int64, pairs combine into huge values (prob. of a
// false positive across 16 probes is ~1e-80).
// ---------------------------------------------------------------------------
__global__ void k_detect(const void* __restrict__ eidx) {
    const long long* p = (const long long*)eidx;
    int ok = 1;
    #pragma unroll
    for (int i = 0; i < 16; i++) {
        long long v = p[i];
        if (v < 0 || v >= NTOKEN) ok = 0;
    }
    g_is64 = ok;
}

// ---------------------------------------------------------------------------
// K1: zero all accumulators
// ---------------------------------------------------------------------------
__global__ void k_zero() {
    int i = blockIdx.x * blockDim.x + threadIdx.x;          // up to 2.4M
    const int n4 = NTOKEN * NINP / 4;                       // 2,400,000
    float4 z4 = make_float4(0.f, 0.f, 0.f, 0.f);
    if (i < n4) {
        ((float4*)g_y)[i] = z4;
        ((float4*)g_z)[i] = z4;
    }
    if (i < NTOKEN) { g_deg[i] = 0.f; g_c[i] = 0.f; }
    if (i < BMWORDS) g_tokbm[i] = 0u;
}

// ---------------------------------------------------------------------------
// K2: in-degree (counts at dst)
// ---------------------------------------------------------------------------
__global__ void k_deg(const void* __restrict__ eidx) {
    int e = blockIdx.x * blockDim.x + threadIdx.x;
    if (e >= NEDGE) return;
    int d = (int)ld_idx(eidx, (long long)NEDGE + e, g_is64);
    atomicAdd(&g_deg[d], 1.0f);
}

// K2b: token bitmap from `input`
__global__ void k_tokbm(const void* __restrict__ inp) {
    int i = blockIdx.x * blockDim.x + threadIdx.x;
    if (i >= NBL) return;
    int t = (int)ld_idx(inp, i, g_is64);
    atomicOr(&g_tokbm[t >> 5], 1u << (t & 31));
}

// K3: dinv = rsqrt(deg + 1)
__global__ void k_dinv() {
    int i = blockIdx.x * blockDim.x + threadIdx.x;
    if (i < NTOKEN) g_dinv[i] = rsqrtf(g_deg[i] + 1.0f);
}

// ---------------------------------------------------------------------------
// K4: pass 1 edge aggregation: y[d] += norm(s,d) * X[s]   (half-warp / edge)
// ---------------------------------------------------------------------------
__global__ void k_pass1(const void* __restrict__ eidx, const float* __restrict__ X) {
    long long t = (long long)blockIdx.x * blockDim.x + threadIdx.x;
    int lane = (int)(t & 15);
    long long e = t >> 4;
    if (e >= NEDGE) return;
    int is64 = g_is64;
    int s = (int)ld_idx(eidx, e, is64);
    int d = (int)ld_idx(eidx, (long long)NEDGE + e, is64);
    float w = g_dinv[s] * g_dinv[d];
    float4 v = ((const float4*)(X + (long long)s * NINP))[lane];
    v.x *= w; v.y *= w; v.z *= w; v.w *= w;
    red_add_v4(g_y + (long long)d * NINP + lane * 4, v);
}

// K5: pass-1 self-loop term: y[i] += X[i] * dinv[i]^2
__global__ void k_self1(const float* __restrict__ X) {
    long long t = (long long)blockIdx.x * blockDim.x + threadIdx.x;
    int lane = (int)(t & 15);
    long long i = t >> 4;
    if (i >= NTOKEN) return;
    float di = g_dinv[i];
    float w = di * di;
    float4 v  = ((const float4*)(X + i * NINP))[lane];
    float4* yp = (float4*)(g_y + i * NINP);
    float4 y = yp[lane];
    y.x += v.x * w; y.y += v.y * w; y.z += v.z * w; y.w += v.w * w;
    yp[lane] = y;
}

// ---------------------------------------------------------------------------
// K6: pass 2 edge aggregation, restricted to token destinations.
//     z[d] += norm * y[s];  c[d] += norm
// ---------------------------------------------------------------------------
__global__ void k_pass2(const void* __restrict__ eidx) {
    long long t = (long long)blockIdx.x * blockDim.x + threadIdx.x;
    int lane = (int)(t & 15);
    long long e = t >> 4;
    if (e >= NEDGE) return;
    int is64 = g_is64;
    int d = (int)ld_idx(eidx, (long long)NEDGE + e, is64);
    if (!((g_tokbm[d >> 5] >> (d & 31)) & 1u)) return;
    int s = (int)ld_idx(eidx, e, is64);
    float w = g_dinv[s] * g_dinv[d];
    float4 v = ((const float4*)(g_y + (long long)s * NINP))[lane];
    v.x *= w; v.y *= w; v.z *= w; v.w *= w;
    red_add_v4(g_z + (long long)d * NINP + lane * 4, v);
    if (lane == 0) atomicAdd(&g_c[d], w);
}

// K7: pass-2 self term at token nodes: z[i] += y[i]*dinv^2 ; c[i] += dinv^2
__global__ void k_self2() {
    long long t = (long long)blockIdx.x * blockDim.x + threadIdx.x;
    int lane = (int)(t & 15);
    long long i = t >> 4;
    if (i >= NTOKEN) return;
    if (!((g_tokbm[i >> 5] >> ((int)i & 31)) & 1u)) return;
    float di = g_dinv[i];
    float w = di * di;
    float4* yp = (float4*)(g_y + i * NINP);
    float4* zp = (float4*)(g_z + i * NINP);
    float4 y = yp[lane];
    float4 z = zp[lane];
    z.x += y.x * w; z.y += y.y * w; z.z += y.z * w; z.w += y.w * w;
    zp[lane] = z;
    if (lane == 0) g_c[i] += w;
}

// ---------------------------------------------------------------------------
// K8: W12 = W1 @ W2 (64x128 @ 128x64), bW = b1 @ W2. 65 blocks x 64 threads.
// ---------------------------------------------------------------------------
__global__ void k_w12(const float* __restrict__ W1, const float* __restrict__ b1,
                      const float* __restrict__ W2) {
    int j = threadIdx.x;
    int b = blockIdx.x;
    float acc = 0.f;
    if (b < NINP) {
        #pragma unroll 8
        for (int k = 0; k < 2 * NINP; k++) acc += W1[b * 2 * NINP + k] * W2[k * NINP + j];
        g_W12[b * NINP + j] = acc;
    } else {
        #pragma unroll 8
        for (int k = 0; k < 2 * NINP; k++) acc += b1[k] * W2[k * NINP + j];
        g_bW[j] = acc;
    }
}

// ---------------------------------------------------------------------------
// K9: out[n, j] = z[tok_n] . W12[:, j] + c[tok_n]*bW[j] + b2[j]
//     4 tokens per 256-thread block; W12 cached in smem.
// ---------------------------------------------------------------------------
__global__ void k_out(const void* __restrict__ inp, const float* __restrict__ b2,
                      float* __restrict__ out) {
    __shared__ float sW[NINP * NINP];
    __shared__ float sz[4][NINP];
    __shared__ float sc[4];
    int tid = threadIdx.x;
    int g = tid >> 6;          // token group 0..3
    int j = tid & 63;
    int n = blockIdx.x * 4 + g;
    int is64 = g_is64;

    for (int i = tid; i < NINP * NINP; i += 256) sW[i] = g_W12[i];
    int tok = (int)ld_idx(inp, n, is64);
    sz[g][j] = g_z[(long long)tok * NINP + j];
    if (j == 0) sc[g] = g_c[tok];
    __syncthreads();

    float acc = 0.f;
    #pragma unroll
    for (int i = 0; i < NINP; i++) acc += sz[g][i] * sW[i * NINP + j];
    out[(long long)n * NINP + j] = acc + sc[g] * g_bW[j] + b2[j];
}

// ---------------------------------------------------------------------------
// Launch
// ---------------------------------------------------------------------------
extern "C" void kernel_launch(void* const* d_in, const int* in_sizes, int n_in,
                              void* d_out, int out_size) {
    const float* emb = (const float*)d_in[0];
    const float* W1  = (const float*)d_in[1];
    const float* b1  = (const float*)d_in[2];
    const float* W2  = (const float*)d_in[3];
    const float* b2  = (const float*)d_in[4];
    const void*  inp = d_in[5];
    // d_in[6] = input_timestamp (unused by the reference output)
    const void*  eidx = d_in[7];
    float* out = (float*)d_out;

    const int TB = 256;
    k_detect<<<1, 1>>>(eidx);
    k_zero<<<(NTOKEN * NINP / 4 + TB - 1) / TB, TB>>>();
    k_deg<<<(NEDGE + TB - 1) / TB, TB>>>(eidx);
    k_tokbm<<<(NBL + TB - 1) / TB, TB>>>(inp);
    k_dinv<<<(NTOKEN + TB - 1) / TB, TB>>>();
    k_pass1<<<(int)(((long long)NEDGE * 16 + TB - 1) / TB), TB>>>(eidx, emb);
    k_self1<<<(int)(((long long)NTOKEN * 16 + TB - 1) / TB), TB>>>(emb);
    k_pass2<<<(int)(((long long)NEDGE * 16 + TB - 1) / TB), TB>>>(eidx);
    k_self2<<<(int)(((long long)NTOKEN * 16 + TB - 1) / TB), TB>>>();
    k_w12<<<NINP + 1, NINP>>>(W1, b1, W2);
    k_out<<<NBL / 4, TB>>>(inp, b2, out);
}

// round 2
// speedup vs baseline: 1.1786x; 1.1786x over previous
#include <cuda_runtime.h>
#include <cuda_bf16.h>

#define NTOKEN 150000
#define NINP   64
#define NEDGE  2400000
#define NBL    12800            // B*L
#define BMWORDS ((NTOKEN + 31) / 32)

// ---------------------------------------------------------------------------
// Scratch
// ---------------------------------------------------------------------------
__device__ __align__(16) float g_y[NTOKEN * NINP];   // P X
__device__ __align__(16) float g_z[NTOKEN * NINP];   // P (P X) — valid at token rows only
__device__ float    g_deg[NTOKEN];
__device__ float    g_dinv[NTOKEN];
__device__ float    g_c[NTOKEN];                     // valid at token rows only
__device__ unsigned g_tokbm[BMWORDS];                // token nodes
__device__ unsigned g_bmneed[BMWORDS];               // nodes whose y is later read
__device__ int2     g_ce[NEDGE];                     // compacted token-dst edges (s,d)
__device__ int      g_cnt;                           // compacted count
__device__ float    g_W12[NINP * NINP];
__device__ float    g_bW[NINP];
__device__ int      g_is64;

// ---------------------------------------------------------------------------
__device__ __forceinline__ long long ld_idx(const void* p, long long i, int is64) {
    return is64 ? ((const long long*)p)[i] : (long long)((const int*)p)[i];
}
__device__ __forceinline__ void red_add_v4(float* p, float4 v) {
    asm volatile("red.global.add.v4.f32 [%0], {%1,%2,%3,%4};"
                 :: "l"(p), "f"(v.x), "f"(v.y), "f"(v.z), "f"(v.w) : "memory");
}

// K0: int64 vs int32 storage detection (16 probes; false positive ~impossible)
__global__ void k_detect(const void* __restrict__ eidx) {
    const long long* p = (const long long*)eidx;
    int ok = 1;
    #pragma unroll
    for (int i = 0; i < 16; i++) {
        long long v = p[i];
        if (v < 0 || v >= NTOKEN) ok = 0;
    }
    g_is64 = ok;
}

// K1: zero y, deg, bitmaps, counter
__global__ void k_zero() {
    int i = blockIdx.x * blockDim.x + threadIdx.x;
    const int n4 = NTOKEN * NINP / 4;
    if (i < n4) ((float4*)g_y)[i] = make_float4(0.f, 0.f, 0.f, 0.f);
    if (i < NTOKEN) g_deg[i] = 0.f;
    if (i < BMWORDS) { g_tokbm[i] = 0u; g_bmneed[i] = 0u; }
    if (i == 0) g_cnt = 0;
}

// K2: token bitmap (tokbm and bmneed — token rows also need y for the self term)
__global__ void k_tokbm(const void* __restrict__ inp) {
    int i = blockIdx.x * blockDim.x + threadIdx.x;
    if (i >= NBL) return;
    int t = (int)ld_idx(inp, i, g_is64);
    atomicOr(&g_tokbm[t >> 5], 1u << (t & 31));
    atomicOr(&g_bmneed[t >> 5], 1u << (t & 31));
}

// K2b: zero z rows + c at token rows (idempotent under duplicates)
__global__ void k_ztok(const void* __restrict__ inp) {
    long long t = (long long)blockIdx.x * blockDim.x + threadIdx.x;
    int l = (int)(t & 15);
    long long n = t >> 4;
    if (n >= NBL) return;
    int tok = (int)ld_idx(inp, n, g_is64);
    ((float4*)(g_z + (long long)tok * NINP))[l] = make_float4(0.f, 0.f, 0.f, 0.f);
    if (l == 0) g_c[tok] = 0.f;
}

// K3: degree + compaction of token-dst edges + bmneed(src)
__global__ void k_degcompact(const void* __restrict__ eidx) {
    int e = blockIdx.x * blockDim.x + threadIdx.x;
    int is64 = g_is64;
    int s = 0, d = 0;
    bool want = false;
    if (e < NEDGE) {
        s = (int)ld_idx(eidx, e, is64);
        d = (int)ld_idx(eidx, (long long)NEDGE + e, is64);
        atomicAdd(&g_deg[d], 1.0f);
        want = (g_tokbm[d >> 5] >> (d & 31)) & 1u;
    }
    unsigned m = __ballot_sync(0xffffffffu, want);
    if (want) {
        int lane = threadIdx.x & 31;
        int leader = __ffs(m) - 1;
        int pos = 0;
        if (lane == leader) pos = atomicAdd(&g_cnt, __popc(m));
        pos = __shfl_sync(m, pos, leader);
        pos += __popc(m & ((1u << lane) - 1u));
        g_ce[pos] = make_int2(s, d);
        atomicOr(&g_bmneed[s >> 5], 1u << (s & 31));
    }
}

// K4: dinv
__global__ void k_dinv() {
    int i = blockIdx.x * blockDim.x + threadIdx.x;
    if (i < NTOKEN) g_dinv[i] = rsqrtf(g_deg[i] + 1.0f);
}

// K5: pass 1 — y[d] += w * X[s], only for d in bmneed.
// 2 edges per warp; lane 0 / lane 16 do scalar loads, shfl broadcast.
__global__ void k_pass1(const void* __restrict__ eidx, const float* __restrict__ X) {
    long long t = (long long)blockIdx.x * blockDim.x + threadIdx.x;
    int lane = threadIdx.x & 31;
    int sub = lane >> 4;
    int l = lane & 15;
    long long e = (t >> 5) * 2 + sub;
    int is64 = g_is64;
    int s = 0, d = 0, pred = 0;
    float w = 0.f;
    if (l == 0 && e < NEDGE) {
        s = (int)ld_idx(eidx, e, is64);
        d = (int)ld_idx(eidx, (long long)NEDGE + e, is64);
        pred = (g_bmneed[d >> 5] >> (d & 31)) & 1u;
        if (pred) w = g_dinv[s] * g_dinv[d];
    }
    int srclane = sub << 4;
    pred = __shfl_sync(0xffffffffu, pred, srclane);
    s    = __shfl_sync(0xffffffffu, s, srclane);
    d    = __shfl_sync(0xffffffffu, d, srclane);
    w    = __shfl_sync(0xffffffffu, w, srclane);
    if (!pred || e >= NEDGE) return;
    float4 v = ((const float4*)(X + (long long)s * NINP))[l];
    v.x *= w; v.y *= w; v.z *= w; v.w *= w;
    red_add_v4(g_y + (long long)d * NINP + l * 4, v);
}

// K6: pass-1 self term at bmneed rows
__global__ void k_self1(const float* __restrict__ X) {
    long long t = (long long)blockIdx.x * blockDim.x + threadIdx.x;
    int l = (int)(t & 15);
    long long i = t >> 4;
    if (i >= NTOKEN) return;
    if (!((g_bmneed[i >> 5] >> ((int)i & 31)) & 1u)) return;
    float di = g_dinv[i];
    float w = di * di;
    float4 v = ((const float4*)(X + i * NINP))[l];
    float4* yp = (float4*)(g_y + i * NINP);
    float4 y = yp[l];
    y.x += v.x * w; y.y += v.y * w; y.z += v.z * w; y.w += v.w * w;
    yp[l] = y;
}

// K7: pass 2 over compacted edges (grid-stride, 16 lanes/edge)
__global__ void k_pass2() {
    int cnt = g_cnt;
    int l = threadIdx.x & 15;
    int gid = (int)(((long long)blockIdx.x * blockDim.x + threadIdx.x) >> 4);
    int stride = (gridDim.x * blockDim.x) >> 4;
    for (int e = gid; e < cnt; e += stride) {
        int2 sd = g_ce[e];
        float w = g_dinv[sd.x] * g_dinv[sd.y];
        float4 v = ((const float4*)(g_y + (long long)sd.x * NINP))[l];
        v.x *= w; v.y *= w; v.z *= w; v.w *= w;
        red_add_v4(g_z + (long long)sd.y * NINP + l * 4, v);
        if (l == 0) atomicAdd(&g_c[sd.y], w);
    }
}

// K8: pass-2 self term at token rows
__global__ void k_self2() {
    long long t = (long long)blockIdx.x * blockDim.x + threadIdx.x;
    int l = (int)(t & 15);
    long long i = t >> 4;
    if (i >= NTOKEN) return;
    if (!((g_tokbm[i >> 5] >> ((int)i & 31)) & 1u)) return;
    float di = g_dinv[i];
    float w = di * di;
    float4 y = ((const float4*)(g_y + i * NINP))[l];
    float4* zp = (float4*)(g_z + i * NINP);
    float4 z = zp[l];
    z.x += y.x * w; z.y += y.y * w; z.z += y.z * w; z.w += y.w * w;
    zp[l] = z;
    if (l == 0) g_c[i] += w;
}

// K9: W12 = W1@W2, bW = b1@W2
__global__ void k_w12(const float* __restrict__ W1, const float* __restrict__ b1,
                      const float* __restrict__ W2) {
    int j = threadIdx.x;
    int b = blockIdx.x;
    float acc = 0.f;
    if (b < NINP) {
        #pragma unroll 8
        for (int k = 0; k < 2 * NINP; k++) acc += W1[b * 2 * NINP + k] * W2[k * NINP + j];
        g_W12[b * NINP + j] = acc;
    } else {
        #pragma unroll 8
        for (int k = 0; k < 2 * NINP; k++) acc += b1[k] * W2[k * NINP + j];
        g_bW[j] = acc;
    }
}

// K10: out[n,j] = z[tok].W12[:,j] + c[tok]*bW[j] + b2[j]
__global__ void k_out(const void* __restrict__ inp, const float* __restrict__ b2,
                      float* __restrict__ out) {
    __shared__ float sW[NINP * NINP];
    __shared__ float sz[4][NINP];
    __shared__ float sc[4];
    int tid = threadIdx.x;
    int g = tid >> 6;
    int j = tid & 63;
    int n = blockIdx.x * 4 + g;
    int is64 = g_is64;

    for (int i = tid; i < NINP * NINP; i += 256) sW[i] = g_W12[i];
    int tok = (int)ld_idx(inp, n, is64);
    sz[g][j] = g_z[(long long)tok * NINP + j];
    if (j == 0) sc[g] = g_c[tok];
    __syncthreads();

    float acc = 0.f;
    #pragma unroll
    for (int i = 0; i < NINP; i++) acc += sz[g][i] * sW[i * NINP + j];
    out[(long long)n * NINP + j] = acc + sc[g] * g_bW[j] + b2[j];
}

// ---------------------------------------------------------------------------
extern "C" void kernel_launch(void* const* d_in, const int* in_sizes, int n_in,
                              void* d_out, int out_size) {
    const float* emb = (const float*)d_in[0];
    const float* W1  = (const float*)d_in[1];
    const float* b1  = (const float*)d_in[2];
    const float* W2  = (const float*)d_in[3];
    const float* b2  = (const float*)d_in[4];
    const void*  inp = d_in[5];
    const void*  eidx = d_in[7];
    float* out = (float*)d_out;

    const int TB = 256;
    k_detect<<<1, 1>>>(eidx);
    k_zero<<<(NTOKEN * NINP / 4 + TB - 1) / TB, TB>>>();
    k_tokbm<<<(NBL + TB - 1) / TB, TB>>>(inp);
    k_ztok<<<(NBL * 16 + TB - 1) / TB, TB>>>(inp);
    k_degcompact<<<(NEDGE + TB - 1) / TB, TB>>>(eidx);
    k_dinv<<<(NTOKEN + TB - 1) / TB, TB>>>();
    k_pass1<<<(int)(((long long)NEDGE * 16 + TB - 1) / TB), TB>>>(eidx, emb);
    k_self1<<<(int)(((long long)NTOKEN * 16 + TB - 1) / TB), TB>>>(emb);
    k_pass2<<<1024, TB>>>();
    k_self2<<<(int)(((long long)NTOKEN * 16 + TB - 1) / TB), TB>>>();
    k_w12<<<NINP + 1, NINP>>>(W1, b1, W2);
    k_out<<<NBL / 4, TB>>>(inp, b2, out);
}